// round 1
// baseline (speedup 1.0000x reference)
#include <cuda_runtime.h>
#include <math.h>

#define Bsz 32
#define Csz 40000
#define Dsz 2048
#define BN  128
#define BK  16

// ---------------- device scratch (no allocations allowed) ----------------
__device__ float    g_A[64 * Dsz];     // rows 0-31: inputs, rows 32-63: V[targets]
__device__ float    g_ni[Bsz * Dsz];   // normalized inputs
__device__ float    g_nth[Bsz];        // dot(ni[b], V[targets[b]]) - N_MARGIN
__device__ unsigned g_rowmax[Bsz];     // ordered-uint encoded row max of outputs
__device__ float    g_th_sum;
__device__ unsigned g_th_cnt;
__device__ float    g_bu;
__device__ int      g_active;
__device__ float    g_out[(size_t)Bsz * Csz]; // outputs scratch (also copied to d_out)

// ordered-uint encoding so atomicMax works for signed floats
__device__ __forceinline__ unsigned encf(float f) {
    unsigned b = __float_as_uint(f);
    return (b & 0x80000000u) ? ~b : (b | 0x80000000u);
}
__device__ __forceinline__ float decf(unsigned u) {
    return (u & 0x80000000u) ? __uint_as_float(u ^ 0x80000000u)
                             : __uint_as_float(~u);
}

// ---------------- prep: normalize inputs, gather V[targets], init accumulators ----
__global__ void prep_kernel(const float* __restrict__ inputs,
                            const float* __restrict__ V,
                            const int* __restrict__ targets) {
    __shared__ float sh[8];
    __shared__ float s_norm;
    int b = blockIdx.x, tid = threadIdx.x;
    const float* x = inputs + b * Dsz;

    float ss = 0.f;
    for (int k = tid; k < Dsz; k += 256) {
        float v = x[k];
        g_A[b * Dsz + k] = v;
        ss += v * v;
    }
    #pragma unroll
    for (int o = 16; o; o >>= 1) ss += __shfl_xor_sync(0xffffffffu, ss, o);
    if ((tid & 31) == 0) sh[tid >> 5] = ss;
    __syncthreads();
    if (tid == 0) {
        float t = 0.f;
        for (int i = 0; i < 8; i++) t += sh[i];
        s_norm = sqrtf(t);
    }
    __syncthreads();
    float inv = 1.f / s_norm;

    int tb = targets[b];
    const float* vt = V + (size_t)tb * Dsz;
    float dot = 0.f;
    for (int k = tid; k < Dsz; k += 256) {
        float nv = x[k] * inv;
        g_ni[b * Dsz + k] = nv;
        float w = vt[k];
        g_A[(size_t)(32 + b) * Dsz + k] = w;
        dot += nv * w;
    }
    #pragma unroll
    for (int o = 16; o; o >>= 1) dot += __shfl_xor_sync(0xffffffffu, dot, o);
    __syncthreads();
    if ((tid & 31) == 0) sh[tid >> 5] = dot;
    __syncthreads();
    if (tid == 0) {
        float t = 0.f;
        for (int i = 0; i < 8; i++) t += sh[i];
        g_nth[b] = t - 0.3f;                 // N_MARGIN
        g_rowmax[b] = 0x007FFFFFu;           // enc(-inf)
        if (b == 0) { g_th_sum = 0.f; g_th_cnt = 0u; g_bu = 0.f; g_active = 1; }
    }
}

// ---------------- fused GEMM: [64 x 2048] x [2048 x 40000] + epilogues ------------
// rows 0-31 -> outputs (x10, row-max for softmax), rows 32-63 -> th masked softplus
__global__ void __launch_bounds__(256)
gemm_kernel(const float* __restrict__ V, float* __restrict__ outp, int write_out) {
    __shared__ float As[BK][64];
    __shared__ float Bs[BK][BN];

    int tid = threadIdx.x;
    int j0 = blockIdx.x * BN;
    int tx = tid & 15, ty = tid >> 4;
    int lane = tid & 31;

    // load mapping
    int am = tid >> 2, q = tid & 3;          // A: one float4 per thread
    int bn0 = tid >> 2, bn1 = bn0 + 64;      // B: two float4s per thread
    int jg0 = j0 + bn0, jg1 = j0 + bn1;
    const float* ar  = g_A + (size_t)am * Dsz + q * 4;
    const float* vr0 = V + (size_t)min(jg0, Csz - 1) * Dsz + q * 4;
    const float* vr1 = V + (size_t)min(jg1, Csz - 1) * Dsz + q * 4;

    float acc[4][8];
    #pragma unroll
    for (int i = 0; i < 4; i++)
        #pragma unroll
        for (int j = 0; j < 8; j++) acc[i][j] = 0.f;
    float rs0 = 0.f, rs1 = 0.f;

    for (int k0 = 0; k0 < Dsz; k0 += BK) {
        float4 av = *(const float4*)(ar + k0);
        float4 b0 = *(const float4*)(vr0 + k0);
        float4 b1 = *(const float4*)(vr1 + k0);
        __syncthreads();
        As[q * 4 + 0][am] = av.x; As[q * 4 + 1][am] = av.y;
        As[q * 4 + 2][am] = av.z; As[q * 4 + 3][am] = av.w;
        Bs[q * 4 + 0][bn0] = b0.x; Bs[q * 4 + 1][bn0] = b0.y;
        Bs[q * 4 + 2][bn0] = b0.z; Bs[q * 4 + 3][bn0] = b0.w;
        Bs[q * 4 + 0][bn1] = b1.x; Bs[q * 4 + 1][bn1] = b1.y;
        Bs[q * 4 + 2][bn1] = b1.z; Bs[q * 4 + 3][bn1] = b1.w;
        rs0 += b0.x + b0.y + b0.z + b0.w;
        rs1 += b1.x + b1.y + b1.z + b1.w;
        __syncthreads();
        #pragma unroll
        for (int kk = 0; kk < BK; kk++) {
            float a[4], bb[8];
            *(float4*)a        = *(const float4*)&As[kk][ty * 4];
            *(float4*)bb       = *(const float4*)&Bs[kk][tx * 8];
            *(float4*)(bb + 4) = *(const float4*)&Bs[kk][tx * 8 + 4];
            #pragma unroll
            for (int i = 0; i < 4; i++)
                #pragma unroll
                for (int j = 0; j < 8; j++)
                    acc[i][j] = fmaf(a[i], bb[j], acc[i][j]);
        }
    }

    // 'active' check: each V row's sum split over 4 q-threads -> combine
    rs0 += __shfl_xor_sync(0xffffffffu, rs0, 1);
    rs0 += __shfl_xor_sync(0xffffffffu, rs0, 2);
    rs1 += __shfl_xor_sync(0xffffffffu, rs1, 1);
    rs1 += __shfl_xor_sync(0xffffffffu, rs1, 2);
    if (q == 0) {
        if (jg0 < Csz && rs0 == 0.f) g_active = 0;
        if (jg1 < Csz && rs1 == 0.f) g_active = 0;
    }

    if (ty < 8) {
        // outputs rows: store x10 and track row max
        #pragma unroll
        for (int i = 0; i < 4; i++) {
            int b = ty * 4 + i;
            float rmax = -INFINITY;
            #pragma unroll
            for (int j = 0; j < 8; j++) {
                int col = j0 + tx * 8 + j;
                if (col < Csz) {
                    float v = acc[i][j] * 10.f;
                    g_out[(size_t)b * Csz + col] = v;
                    if (write_out) outp[(size_t)b * Csz + col] = v;
                    rmax = fmaxf(rmax, v);
                }
            }
            #pragma unroll
            for (int o = 1; o < 16; o <<= 1)
                rmax = fmaxf(rmax, __shfl_xor_sync(0xffffffffu, rmax, o));
            if (tx == 0) atomicMax(&g_rowmax[b], encf(rmax));
        }
    } else {
        // nsims_t rows: masked softplus accumulation for th_loss
        float lsum = 0.f; unsigned lcnt = 0u;
        #pragma unroll
        for (int i = 0; i < 4; i++) {
            int b = ty * 4 + i - 32;
            float nth = g_nth[b];
            #pragma unroll
            for (int j = 0; j < 8; j++) {
                int col = j0 + tx * 8 + j;
                if (col < Csz) {
                    float s = acc[i][j];
                    if (nth < s && s < 0.9999f) { lsum += log1pf(expf(s)); lcnt++; }
                }
            }
        }
        #pragma unroll
        for (int o = 16; o; o >>= 1) {
            lsum += __shfl_xor_sync(0xffffffffu, lsum, o);
            lcnt += __shfl_xor_sync(0xffffffffu, lcnt, o);
        }
        if (lane == 0) { atomicAdd(&g_th_sum, lsum); atomicAdd(&g_th_cnt, lcnt); }
    }
}

// ---------------- per-row logsumexp over outputs (L2-resident) + bu accumulation --
__global__ void lse_kernel(const int* __restrict__ targets) {
    __shared__ float sh[8];
    int b = blockIdx.x, tid = threadIdx.x;
    float m = decf(g_rowmax[b]);
    const float* row = g_out + (size_t)b * Csz;
    float s = 0.f;
    for (int j = tid; j < Csz; j += 256) s += expf(row[j] - m);
    #pragma unroll
    for (int o = 16; o; o >>= 1) s += __shfl_xor_sync(0xffffffffu, s, o);
    if ((tid & 31) == 0) sh[tid >> 5] = s;
    __syncthreads();
    if (tid == 0) {
        float t = 0.f;
        for (int i = 0; i < 8; i++) t += sh[i];
        float lse = m + logf(t);
        atomicAdd(&g_bu, lse - row[targets[b]]);
    }
}

// ---------------- final: 32x32 sims, h_loss, assemble loss ------------------------
__global__ void final_kernel(const int* __restrict__ targets, float* loss_out) {
    __shared__ float sims[32][33];
    __shared__ int tg[32];
    int tid = threadIdx.x;
    if (tid < 32) tg[tid] = targets[tid];
    __syncthreads();
    for (int p = tid; p < 1024; p += 256) {
        int i = p >> 5, j = p & 31;
        const float4* a = (const float4*)(g_ni + (size_t)i * Dsz);
        const float4* c = (const float4*)(g_ni + (size_t)j * Dsz);
        float d = 0.f;
        for (int k = 0; k < Dsz / 4; k++) {
            float4 x = a[k], y = c[k];
            d += x.x * y.x + x.y * y.y + x.z * y.z + x.w * y.w;
        }
        sims[i][j] = d;
    }
    __syncthreads();
    if (tid < 32) {
        int i = tid;
        float mn = 2.f, mx = -2.f;
        for (int j = 0; j < 32; j++) {
            bool pos = (tg[i] == tg[j]) && (i != j);
            float s = sims[i][j];
            if (pos) { mn = fminf(mn, s); mx = fmaxf(mx, s); }
        }
        float nthr = mn - 0.3f;   // N_MARGIN
        float pthr = mx - 0.2f;   // P_MARGIN
        float ps = 0.f, ns = 0.f, pc = 0.f, nc = 0.f;
        for (int j = 0; j < 32; j++) {
            float s = sims[i][j];
            bool same = (tg[i] == tg[j]);
            bool pos = same && (i != j);
            if (pos && s < pthr)   { ps += log1pf(expf(-s)); pc += 1.f; }
            if (!same && s > nthr) { ns += log1pf(expf(s));  nc += 1.f; }
        }
        #pragma unroll
        for (int o = 16; o; o >>= 1) {
            ps += __shfl_xor_sync(0xffffffffu, ps, o);
            ns += __shfl_xor_sync(0xffffffffu, ns, o);
            pc += __shfl_xor_sync(0xffffffffu, pc, o);
            nc += __shfl_xor_sync(0xffffffffu, nc, o);
        }
        if (i == 0) {
            float h  = (pc > 0.f ? ps / pc : 0.f) + (nc > 0.f ? ns / nc : 0.f);
            float th = (g_active && g_th_cnt > 0u) ? g_th_sum / (float)g_th_cnt : 0.f;
            float bu = g_bu * (1.f / 32.f);
            float loss = bu + h + 3.f * th;   // W_BU*bu + W_H*h + W_TH*th
            if (loss_out) loss_out[0] = loss;
        }
    }
}

// ---------------- launch ----------------------------------------------------------
extern "C" void kernel_launch(void* const* d_in, const int* in_sizes, int n_in,
                              void* d_out, int out_size) {
    const float* inputs  = (const float*)d_in[0];
    const float* V       = (const float*)d_in[1];
    const int*   targets = (const int*)d_in[2];
    float* out = (float*)d_out;

    const int BC = Bsz * Csz;
    int write_out = (out_size >= BC) ? 1 : 0;
    int off = write_out ? (out_size - BC) : 0;          // expected: 1 (loss first)
    float* outp = write_out ? (out + off) : nullptr;
    float* loss_out = (off >= 1 || out_size < BC) ? out : nullptr;

    prep_kernel<<<32, 256>>>(inputs, V, targets);
    gemm_kernel<<<(Csz + BN - 1) / BN, 256>>>(V, outp, write_out);
    lse_kernel<<<32, 256>>>(targets);
    final_kernel<<<1, 256>>>(targets, loss_out);
}

// round 3
// speedup vs baseline: 4.1265x; 4.1265x over previous
#include <cuda_runtime.h>
#include <math.h>

#define Bsz 32
#define Csz 40000
#define Dsz 2048
#define BN  128
#define BK  32

// ---------------- device scratch ----------------
__device__ float    g_A[64 * Dsz];     // rows 0-31: inputs, rows 32-63: V[targets]
__device__ float    g_ni[Bsz * Dsz];   // normalized inputs
__device__ float    g_nth[Bsz];        // dot(ni[b], V[targets[b]]) - N_MARGIN
__device__ unsigned g_rowmax[Bsz];     // ordered-uint row max of outputs
__device__ float    g_expsum[Bsz];
__device__ float    g_sims[Bsz * Bsz];
__device__ float    g_th_sum;
__device__ unsigned g_th_cnt;
__device__ int      g_active;
__device__ float    g_out[(size_t)Bsz * Csz];

__device__ __forceinline__ unsigned encf(float f) {
    unsigned b = __float_as_uint(f);
    return (b & 0x80000000u) ? ~b : (b | 0x80000000u);
}
__device__ __forceinline__ float decf(unsigned u) {
    return (u & 0x80000000u) ? __uint_as_float(u ^ 0x80000000u)
                             : __uint_as_float(~u);
}
__device__ __forceinline__ float to_tf32(float x) {
    unsigned r; asm("cvt.rna.tf32.f32 %0, %1;" : "=r"(r) : "f"(x));
    return __uint_as_float(r);
}
__device__ __forceinline__ void mma_tf32(float* c, const unsigned* a,
                                         unsigned b0, unsigned b1) {
    asm volatile(
        "mma.sync.aligned.m16n8k8.row.col.f32.tf32.tf32.f32 "
        "{%0,%1,%2,%3}, {%4,%5,%6,%7}, {%8,%9}, {%0,%1,%2,%3};"
        : "+f"(c[0]), "+f"(c[1]), "+f"(c[2]), "+f"(c[3])
        : "r"(a[0]), "r"(a[1]), "r"(a[2]), "r"(a[3]), "r"(b0), "r"(b1));
}

// ---------------- prep ----------------
__global__ void prep_kernel(const float* __restrict__ inputs,
                            const float* __restrict__ V,
                            const int* __restrict__ targets) {
    __shared__ float sh[8];
    __shared__ float s_norm;
    int b = blockIdx.x, tid = threadIdx.x;
    const float* x = inputs + b * Dsz;

    float ss = 0.f;
    for (int k = tid; k < Dsz; k += 256) {
        float v = x[k];
        g_A[b * Dsz + k] = v;
        ss += v * v;
    }
    #pragma unroll
    for (int o = 16; o; o >>= 1) ss += __shfl_xor_sync(0xffffffffu, ss, o);
    if ((tid & 31) == 0) sh[tid >> 5] = ss;
    __syncthreads();
    if (tid == 0) {
        float t = 0.f;
        for (int i = 0; i < 8; i++) t += sh[i];
        s_norm = sqrtf(t);
    }
    __syncthreads();
    float inv = 1.f / s_norm;

    int tb = targets[b];
    const float* vt = V + (size_t)tb * Dsz;
    float dot = 0.f;
    for (int k = tid; k < Dsz; k += 256) {
        float nv = x[k] * inv;
        g_ni[b * Dsz + k] = nv;
        float w = vt[k];
        g_A[(size_t)(32 + b) * Dsz + k] = w;
        dot += nv * w;
    }
    #pragma unroll
    for (int o = 16; o; o >>= 1) dot += __shfl_xor_sync(0xffffffffu, dot, o);
    __syncthreads();
    if ((tid & 31) == 0) sh[tid >> 5] = dot;
    __syncthreads();
    if (tid == 0) {
        float t = 0.f;
        for (int i = 0; i < 8; i++) t += sh[i];
        g_nth[b] = t - 0.3f;
        g_rowmax[b] = 0u;
        g_expsum[b] = 0.f;
        if (b == 0) { g_th_sum = 0.f; g_th_cnt = 0u; g_active = 1; }
    }
}

// ---------------- tensor-core GEMM: [64 x 2048] x [2048 x 40000]^T ----------------
__global__ void __launch_bounds__(256)
gemm_tc(const float* __restrict__ V, float* __restrict__ outp, int write_out) {
    __shared__ float As[64][36];
    __shared__ float Vs[128][36];
    __shared__ unsigned s_rmax[32];

    int tid = threadIdx.x;
    int lane = tid & 31, w = tid >> 5;
    int g = lane >> 2, t4 = lane & 3;
    int j0 = blockIdx.x * BN;

    // loaders
    int arow = tid >> 2, acol = (tid & 3) * 8;   // A: 8 floats per thread
    int vrow = tid >> 1, vcol = (tid & 1) * 16;  // V: 16 floats per thread
    int jg = j0 + vrow;
    const float* aptr = g_A + (size_t)arow * Dsz + acol;
    const float* vptr = V + (size_t)(jg < Csz ? jg : Csz - 1) * Dsz + vcol;

    float acc[4][2][4];
    #pragma unroll
    for (int i = 0; i < 4; i++)
        #pragma unroll
        for (int j = 0; j < 2; j++)
            #pragma unroll
            for (int k = 0; k < 4; k++) acc[i][j][k] = 0.f;
    float rowsum = 0.f;

    float4 aR0 = *(const float4*)(aptr);
    float4 aR1 = *(const float4*)(aptr + 4);
    float4 vR[4];
    #pragma unroll
    for (int i = 0; i < 4; i++) vR[i] = *(const float4*)(vptr + i * 4);

    for (int k0 = 0; k0 < Dsz; k0 += BK) {
        __syncthreads();
        As[arow][acol + 0] = to_tf32(aR0.x); As[arow][acol + 1] = to_tf32(aR0.y);
        As[arow][acol + 2] = to_tf32(aR0.z); As[arow][acol + 3] = to_tf32(aR0.w);
        As[arow][acol + 4] = to_tf32(aR1.x); As[arow][acol + 5] = to_tf32(aR1.y);
        As[arow][acol + 6] = to_tf32(aR1.z); As[arow][acol + 7] = to_tf32(aR1.w);
        #pragma unroll
        for (int i = 0; i < 4; i++) {
            Vs[vrow][vcol + i * 4 + 0] = to_tf32(vR[i].x);
            Vs[vrow][vcol + i * 4 + 1] = to_tf32(vR[i].y);
            Vs[vrow][vcol + i * 4 + 2] = to_tf32(vR[i].z);
            Vs[vrow][vcol + i * 4 + 3] = to_tf32(vR[i].w);
            rowsum += vR[i].x + vR[i].y + vR[i].z + vR[i].w;
        }
        __syncthreads();
        if (k0 + BK < Dsz) {
            aR0 = *(const float4*)(aptr + k0 + BK);
            aR1 = *(const float4*)(aptr + k0 + BK + 4);
            #pragma unroll
            for (int i = 0; i < 4; i++) vR[i] = *(const float4*)(vptr + k0 + BK + i * 4);
        }
        #pragma unroll
        for (int kk = 0; kk < 4; kk++) {
            int kb = kk * 8;
            unsigned af[4][4];
            #pragma unroll
            for (int mt = 0; mt < 4; mt++) {
                af[mt][0] = __float_as_uint(As[mt * 16 + g][kb + t4]);
                af[mt][1] = __float_as_uint(As[mt * 16 + 8 + g][kb + t4]);
                af[mt][2] = __float_as_uint(As[mt * 16 + g][kb + 4 + t4]);
                af[mt][3] = __float_as_uint(As[mt * 16 + 8 + g][kb + 4 + t4]);
            }
            #pragma unroll
            for (int nt = 0; nt < 2; nt++) {
                unsigned b0 = __float_as_uint(Vs[w * 16 + nt * 8 + g][kb + t4]);
                unsigned b1 = __float_as_uint(Vs[w * 16 + nt * 8 + g][kb + 4 + t4]);
                #pragma unroll
                for (int mt = 0; mt < 4; mt++)
                    mma_tf32(acc[mt][nt], af[mt], b0, b1);
            }
        }
    }

    // 'active' check (row sums of V)
    rowsum += __shfl_xor_sync(0xffffffffu, rowsum, 1);
    if ((tid & 1) == 0 && jg < Csz && rowsum == 0.f) g_active = 0;

    if (tid < 32) s_rmax[tid] = 0u;
    __syncthreads();

    int colbase = j0 + w * 16 + 2 * t4;

    // rows 0-31: outputs x10, row max
    #pragma unroll
    for (int mt = 0; mt < 2; mt++) {
        #pragma unroll
        for (int half = 0; half < 2; half++) {
            int row = mt * 16 + half * 8 + g;
            float rmax = -3.0e38f;
            #pragma unroll
            for (int nt = 0; nt < 2; nt++) {
                int c0 = colbase + nt * 8;
                float o0 = acc[mt][nt][half * 2 + 0] * 10.f;
                float o1 = acc[mt][nt][half * 2 + 1] * 10.f;
                if (c0 < Csz) {
                    g_out[(size_t)row * Csz + c0] = o0;
                    if (write_out) outp[(size_t)row * Csz + c0] = o0;
                    rmax = fmaxf(rmax, o0);
                }
                if (c0 + 1 < Csz) {
                    g_out[(size_t)row * Csz + c0 + 1] = o1;
                    if (write_out) outp[(size_t)row * Csz + c0 + 1] = o1;
                    rmax = fmaxf(rmax, o1);
                }
            }
            rmax = fmaxf(rmax, __shfl_xor_sync(0xffffffffu, rmax, 1));
            rmax = fmaxf(rmax, __shfl_xor_sync(0xffffffffu, rmax, 2));
            if (t4 == 0) atomicMax(&s_rmax[row], encf(rmax));
        }
    }

    // rows 32-63: th masked softplus
    float th_sum = 0.f; unsigned th_cnt = 0u;
    #pragma unroll
    for (int mt = 2; mt < 4; mt++) {
        #pragma unroll
        for (int half = 0; half < 2; half++) {
            int b = mt * 16 + half * 8 + g - 32;
            float nth = g_nth[b];
            #pragma unroll
            for (int nt = 0; nt < 2; nt++) {
                int c0 = colbase + nt * 8;
                float s0 = acc[mt][nt][half * 2 + 0];
                float s1 = acc[mt][nt][half * 2 + 1];
                if (c0 < Csz && nth < s0 && s0 < 0.9999f) { th_sum += log1pf(expf(s0)); th_cnt++; }
                if (c0 + 1 < Csz && nth < s1 && s1 < 0.9999f) { th_sum += log1pf(expf(s1)); th_cnt++; }
            }
        }
    }
    #pragma unroll
    for (int o = 16; o; o >>= 1) {
        th_sum += __shfl_xor_sync(0xffffffffu, th_sum, o);
        th_cnt += __shfl_xor_sync(0xffffffffu, th_cnt, o);
    }
    if (lane == 0 && th_cnt) { atomicAdd(&g_th_sum, th_sum); atomicAdd(&g_th_cnt, th_cnt); }

    __syncthreads();
    if (tid < 32) atomicMax(&g_rowmax[tid], s_rmax[tid]);
}

// ---------------- exp-sum over outputs, 8 chunks per row ----------------
__global__ void lse_kernel() {
    __shared__ float sh[8];
    int b = blockIdx.x, tid = threadIdx.x;
    float m = decf(g_rowmax[b]);
    const float* row = g_out + (size_t)b * Csz + blockIdx.y * 5000;
    float s = 0.f;
    for (int j = tid; j < 5000; j += 256) s += expf(row[j] - m);
    #pragma unroll
    for (int o = 16; o; o >>= 1) s += __shfl_xor_sync(0xffffffffu, s, o);
    if ((tid & 31) == 0) sh[tid >> 5] = s;
    __syncthreads();
    if (tid == 0) {
        float t = 0.f;
        for (int i = 0; i < 8; i++) t += sh[i];
        atomicAdd(&g_expsum[b], t);
    }
}

// ---------------- 32x32 batch sims (parallel) ----------------
__global__ void sims_kernel() {
    int i = blockIdx.x, tid = threadIdx.x, w = tid >> 5, lane = tid & 31;
    const float4* a = (const float4*)(g_ni + (size_t)i * Dsz);
    for (int j = w; j < 32; j += 8) {
        const float4* c = (const float4*)(g_ni + (size_t)j * Dsz);
        float d = 0.f;
        for (int k = lane; k < Dsz / 4; k += 32) {
            float4 x = a[k], y = c[k];
            d += x.x * y.x + x.y * y.y + x.z * y.z + x.w * y.w;
        }
        #pragma unroll
        for (int o = 16; o; o >>= 1) d += __shfl_xor_sync(0xffffffffu, d, o);
        if (lane == 0) g_sims[i * 32 + j] = d;
    }
}

// ---------------- final: h_loss + assemble ----------------
__global__ void final_kernel(const int* __restrict__ targets, float* loss_out) {
    int i = threadIdx.x;  // 32 threads
    int tg = targets[i];
    float m = decf(g_rowmax[i]);
    float bu_i = (m + logf(g_expsum[i])) - g_out[(size_t)i * Csz + tg];

    float mn = 2.f, mx = -2.f;
    for (int j = 0; j < 32; j++) {
        int tgj = __shfl_sync(0xffffffffu, tg, j);
        float s = g_sims[i * 32 + j];
        if (tg == tgj && j != i) { mn = fminf(mn, s); mx = fmaxf(mx, s); }
    }
    float nthr = mn - 0.3f, pthr = mx - 0.2f;
    float ps = 0.f, ns = 0.f, pc = 0.f, nc = 0.f;
    for (int j = 0; j < 32; j++) {
        int tgj = __shfl_sync(0xffffffffu, tg, j);
        float s = g_sims[i * 32 + j];
        bool same = (tg == tgj);
        if (same && j != i && s < pthr) { ps += log1pf(expf(-s)); pc += 1.f; }
        if (!same && s > nthr)          { ns += log1pf(expf(s));  nc += 1.f; }
    }
    #pragma unroll
    for (int o = 16; o; o >>= 1) {
        bu_i += __shfl_xor_sync(0xffffffffu, bu_i, o);
        ps += __shfl_xor_sync(0xffffffffu, ps, o);
        ns += __shfl_xor_sync(0xffffffffu, ns, o);
        pc += __shfl_xor_sync(0xffffffffu, pc, o);
        nc += __shfl_xor_sync(0xffffffffu, nc, o);
    }
    if (i == 0) {
        float h  = (pc > 0.f ? ps / pc : 0.f) + (nc > 0.f ? ns / nc : 0.f);
        float th = (g_active && g_th_cnt > 0u) ? g_th_sum / (float)g_th_cnt : 0.f;
        float loss = bu_i * (1.f / 32.f) + h + 3.f * th;
        if (loss_out) loss_out[0] = loss;
    }
}

// ---------------- launch ----------------
extern "C" void kernel_launch(void* const* d_in, const int* in_sizes, int n_in,
                              void* d_out, int out_size) {
    const float* inputs  = (const float*)d_in[0];
    const float* V       = (const float*)d_in[1];
    const int*   targets = (const int*)d_in[2];
    float* out = (float*)d_out;

    const int BC = Bsz * Csz;
    int write_out = (out_size >= BC) ? 1 : 0;
    int off = write_out ? (out_size - BC) : 0;
    float* outp = write_out ? (out + off) : nullptr;
    float* loss_out = (off >= 1 || out_size < BC) ? out : nullptr;

    prep_kernel<<<32, 256>>>(inputs, V, targets);
    gemm_tc<<<(Csz + BN - 1) / BN, 256>>>(V, outp, write_out);
    lse_kernel<<<dim3(32, 8), 256>>>();
    sims_kernel<<<32, 256>>>();
    final_kernel<<<1, 32>>>(targets, loss_out);
}

// round 5
// speedup vs baseline: 4.7227x; 1.1445x over previous
#include <cuda_runtime.h>
#include <math.h>

#define Bsz  32
#define Csz  40000
#define Dsz  2048
#define NBLK 313          // gemm blocks (ceil(40000/128))
#define NBP  320          // padded partial stride
#define NT   128          // k-tiles of 16 (2048/16)

// ---------------- device scratch ----------------
__device__ float    g_Ap[64 * Dsz];    // permuted tf32 A (rows 0-31 inputs, 32-63 V[targets])
__device__ float    g_ni[Bsz * Dsz];   // normalized inputs
__device__ float    g_nth[Bsz];        // dot(ni[b], V[targets[b]]) - N_MARGIN
__device__ float    g_sims[Bsz * Bsz];
__device__ float    g_pmax[Bsz * NBP]; // per-block row max of logits
__device__ float    g_psum[Bsz * NBP]; // per-block row expsum
__device__ float    g_tgt[Bsz];        // target logit per row
__device__ float    g_th_sum;
__device__ unsigned g_th_cnt;
__device__ int      g_active;

__device__ __forceinline__ unsigned encf(float f) {
    unsigned b = __float_as_uint(f);
    return (b & 0x80000000u) ? ~b : (b | 0x80000000u);
}
__device__ __forceinline__ float decf(unsigned u) {
    return (u & 0x80000000u) ? __uint_as_float(u ^ 0x80000000u)
                             : __uint_as_float(~u);
}
__device__ __forceinline__ float to_tf32(float x) {
    unsigned r; asm("cvt.rna.tf32.f32 %0, %1;" : "=r"(r) : "f"(x));
    return __uint_as_float(r);
}
__device__ __forceinline__ unsigned to_tf32_b(float x) {
    unsigned r; asm("cvt.rna.tf32.f32 %0, %1;" : "=r"(r) : "f"(x));
    return r;
}
__device__ __forceinline__ void mma_tf32(float* c, const unsigned* a,
                                         unsigned b0, unsigned b1) {
    asm volatile(
        "mma.sync.aligned.m16n8k8.row.col.f32.tf32.tf32.f32 "
        "{%0,%1,%2,%3}, {%4,%5,%6,%7}, {%8,%9}, {%0,%1,%2,%3};"
        : "+f"(c[0]), "+f"(c[1]), "+f"(c[2]), "+f"(c[3])
        : "r"(a[0]), "r"(a[1]), "r"(a[2]), "r"(a[3]), "r"(b0), "r"(b1));
}

// permuted A position: fragment-contiguous per (k8-chunk, lane)
__device__ __forceinline__ int apos(int row, int k) {
    int c = k >> 3, t4 = k & 3, hh = (k >> 2) & 1;
    int g = row & 7, rr = (row >> 3) & 1, mt = row >> 4;
    return (c * 32 + g * 4 + t4) * 16 + mt * 4 + hh * 2 + rr;
}

#define CP16(d, s)  asm volatile("cp.async.cg.shared.global [%0],[%1],16;" :: "r"(d), "l"(s))
#define CPCOMMIT()  asm volatile("cp.async.commit_group;")
#define CPWAIT1()   asm volatile("cp.async.wait_group 1;")

// ---------------- prep: normalize inputs, build permuted tf32 A ----------------
__global__ void prep_kernel(const float* __restrict__ inputs,
                            const float* __restrict__ V,
                            const int* __restrict__ targets) {
    __shared__ float sh[8];
    __shared__ float s_norm;
    int b = blockIdx.x, tid = threadIdx.x;
    const float* x = inputs + b * Dsz;

    float ss = 0.f;
    for (int k = tid; k < Dsz; k += 256) {
        float v = x[k];
        g_Ap[apos(b, k)] = to_tf32(v);
        ss += v * v;
    }
    #pragma unroll
    for (int o = 16; o; o >>= 1) ss += __shfl_xor_sync(0xffffffffu, ss, o);
    if ((tid & 31) == 0) sh[tid >> 5] = ss;
    __syncthreads();
    if (tid == 0) {
        float t = 0.f;
        for (int i = 0; i < 8; i++) t += sh[i];
        s_norm = sqrtf(t);
    }
    __syncthreads();
    float inv = 1.f / s_norm;

    int tb = targets[b];
    const float* vt = V + (size_t)tb * Dsz;
    float dot = 0.f;
    for (int k = tid; k < Dsz; k += 256) {
        float nv = x[k] * inv;
        g_ni[b * Dsz + k] = nv;
        float w = vt[k];
        g_Ap[apos(32 + b, k)] = to_tf32(w);
        dot += nv * w;
    }
    #pragma unroll
    for (int o = 16; o; o >>= 1) dot += __shfl_xor_sync(0xffffffffu, dot, o);
    __syncthreads();
    if ((tid & 31) == 0) sh[tid >> 5] = dot;
    __syncthreads();
    if (tid == 0) {
        float t = 0.f;
        for (int i = 0; i < 8; i++) t += sh[i];
        g_nth[b] = t - 0.3f;
        if (b == 0) { g_th_sum = 0.f; g_th_cnt = 0u; g_active = 1; }
    }
}

// ---------------- fused GEMM + softmax partials + th-loss (+sims blocks) ----------
__global__ void __launch_bounds__(256, 2)
fused_gemm(const float* __restrict__ V, const int* __restrict__ targets,
           float* __restrict__ outp, int write_out) {
    __shared__ __align__(16) float As[3][2 * 32 * 20];   // 5120 B/stage
    __shared__ __align__(16) float Vs[3][128 * 20];      // 10240 B/stage
    __shared__ unsigned s_max[32];
    __shared__ float s_sum[32];
    __shared__ int s_tg[32];

    int bx = blockIdx.x;
    int tid = threadIdx.x;

    if (bx >= NBLK) {
        // ---- batch sims (runs in gemm tail shadow) ----
        int i = bx - NBLK;
        int w = tid >> 5, lane = tid & 31;
        const float4* a = (const float4*)(g_ni + (size_t)i * Dsz);
        for (int j = w; j < 32; j += 8) {
            const float4* c = (const float4*)(g_ni + (size_t)j * Dsz);
            float d = 0.f;
            for (int k = lane; k < Dsz / 4; k += 32) {
                float4 x = a[k], y = c[k];
                d += x.x * y.x + x.y * y.y + x.z * y.z + x.w * y.w;
            }
            #pragma unroll
            for (int o = 16; o; o >>= 1) d += __shfl_xor_sync(0xffffffffu, d, o);
            if (lane == 0) g_sims[i * 32 + j] = d;
        }
        return;
    }

    int lane = tid & 31, w = tid >> 5, g = lane >> 2, t4 = lane & 3;
    int j0 = bx * 128;
    if (tid < 32) { s_max[tid] = encf(-3.0e38f); s_sum[tid] = 0.f; s_tg[tid] = targets[tid]; }

    // loader mappings
    int alb = tid >> 2, aj = (tid & 3) * 4;       // A: one 16B chunk / thread / tile
    unsigned a_dst0 = (unsigned)__cvta_generic_to_shared(&As[0][alb * 20 + aj]);
    const float* a_src = g_Ap + tid * 4;
    int vrow = tid >> 1, vj = (tid & 1) * 8;      // V: two 16B chunks / thread / tile
    int jg = j0 + vrow;
    const float* v_src = V + (size_t)(jg < Csz ? jg : Csz - 1) * Dsz + vj;
    unsigned v_dst0 = (unsigned)__cvta_generic_to_shared(&Vs[0][vrow * 20 + vj]);
    const unsigned ASTG = sizeof(As[0]);
    const unsigned VSTG = sizeof(Vs[0]);

    float acc[4][2][4];
    #pragma unroll
    for (int i = 0; i < 4; i++)
        #pragma unroll
        for (int j = 0; j < 2; j++)
            #pragma unroll
            for (int k = 0; k < 4; k++) acc[i][j][k] = 0.f;
    float rs0 = 0.f, rs1 = 0.f;

    // prologue: tiles 0,1 in flight
    #pragma unroll
    for (int t = 0; t < 2; ++t) {
        CP16(a_dst0 + t * ASTG, a_src + t * 1024);
        CP16(v_dst0 + t * VSTG, v_src + t * 16);
        CP16(v_dst0 + t * VSTG + 16, v_src + t * 16 + 4);
        CPCOMMIT();
    }

    for (int t = 0; t < NT; ++t) {
        CPWAIT1();
        __syncthreads();
        int tn = t + 2;
        if (tn < NT) {
            int s2 = tn % 3;
            CP16(a_dst0 + s2 * ASTG, a_src + tn * 1024);
            CP16(v_dst0 + s2 * VSTG, v_src + tn * 16);
            CP16(v_dst0 + s2 * VSTG + 16, v_src + tn * 16 + 4);
        }
        CPCOMMIT();
        int s = t % 3;
        #pragma unroll
        for (int kk = 0; kk < 2; ++kk) {
            const float* ap = &As[s][(kk * 32 + lane) * 20];
            float4 f0 = *(const float4*)(ap);
            float4 f1 = *(const float4*)(ap + 4);
            float4 f2 = *(const float4*)(ap + 8);
            float4 f3 = *(const float4*)(ap + 12);
            unsigned af[4][4];
            af[0][0] = __float_as_uint(f0.x); af[0][1] = __float_as_uint(f0.y);
            af[0][2] = __float_as_uint(f0.z); af[0][3] = __float_as_uint(f0.w);
            af[1][0] = __float_as_uint(f1.x); af[1][1] = __float_as_uint(f1.y);
            af[1][2] = __float_as_uint(f1.z); af[1][3] = __float_as_uint(f1.w);
            af[2][0] = __float_as_uint(f2.x); af[2][1] = __float_as_uint(f2.y);
            af[2][2] = __float_as_uint(f2.z); af[2][3] = __float_as_uint(f2.w);
            af[3][0] = __float_as_uint(f3.x); af[3][1] = __float_as_uint(f3.y);
            af[3][2] = __float_as_uint(f3.z); af[3][3] = __float_as_uint(f3.w);
            #pragma unroll
            for (int nt = 0; nt < 2; ++nt) {
                int vr = w * 16 + nt * 8 + g;
                float braw0 = Vs[s][vr * 20 + kk * 8 + t4];
                float braw1 = Vs[s][vr * 20 + kk * 8 + 4 + t4];
                if (nt == 0) rs0 += braw0 + braw1; else rs1 += braw0 + braw1;
                unsigned b0 = to_tf32_b(braw0), b1 = to_tf32_b(braw1);
                #pragma unroll
                for (int mt = 0; mt < 4; ++mt)
                    mma_tf32(acc[mt][nt], af[mt], b0, b1);
            }
        }
    }

    // 'active' check (exact fp32 row sums of V, accumulated pre-cvt)
    rs0 += __shfl_xor_sync(0xffffffffu, rs0, 1);
    rs0 += __shfl_xor_sync(0xffffffffu, rs0, 2);
    rs1 += __shfl_xor_sync(0xffffffffu, rs1, 1);
    rs1 += __shfl_xor_sync(0xffffffffu, rs1, 2);
    if (t4 == 0) {
        int r0 = j0 + w * 16 + g, r1 = j0 + w * 16 + 8 + g;
        if (r0 < Csz && rs0 == 0.f) g_active = 0;
        if (r1 < Csz && rs1 == 0.f) g_active = 0;
    }

    int colbase = j0 + w * 16 + 2 * t4;

    // phase 1: block-local row maxima (rows 0-31)
    #pragma unroll
    for (int mt = 0; mt < 2; ++mt) {
        #pragma unroll
        for (int half = 0; half < 2; ++half) {
            int row = mt * 16 + half * 8 + g;
            float rmax = -3.0e38f;
            #pragma unroll
            for (int nt = 0; nt < 2; ++nt) {
                int c0 = colbase + nt * 8;
                if (c0 < Csz)     rmax = fmaxf(rmax, acc[mt][nt][half * 2]     * 10.f);
                if (c0 + 1 < Csz) rmax = fmaxf(rmax, acc[mt][nt][half * 2 + 1] * 10.f);
            }
            rmax = fmaxf(rmax, __shfl_xor_sync(0xffffffffu, rmax, 1));
            rmax = fmaxf(rmax, __shfl_xor_sync(0xffffffffu, rmax, 2));
            if (t4 == 0) atomicMax(&s_max[row], encf(rmax));
        }
    }
    __syncthreads();

    // phase 2: expsum, output store, target-logit capture
    #pragma unroll
    for (int mt = 0; mt < 2; ++mt) {
        #pragma unroll
        for (int half = 0; half < 2; ++half) {
            int row = mt * 16 + half * 8 + g;
            float m = decf(s_max[row]);
            int tg = s_tg[row];
            float es = 0.f;
            #pragma unroll
            for (int nt = 0; nt < 2; ++nt) {
                int c0 = colbase + nt * 8;
                float o0 = acc[mt][nt][half * 2]     * 10.f;
                float o1 = acc[mt][nt][half * 2 + 1] * 10.f;
                if (c0 < Csz) {
                    if (write_out) outp[(size_t)row * Csz + c0] = o0;
                    if (c0 == tg) g_tgt[row] = o0;
                    es += expf(o0 - m);
                }
                if (c0 + 1 < Csz) {
                    if (write_out) outp[(size_t)row * Csz + c0 + 1] = o1;
                    if (c0 + 1 == tg) g_tgt[row] = o1;
                    es += expf(o1 - m);
                }
            }
            es += __shfl_xor_sync(0xffffffffu, es, 1);
            es += __shfl_xor_sync(0xffffffffu, es, 2);
            if (t4 == 0) atomicAdd(&s_sum[row], es);
        }
    }

    // th-loss rows (32-63)
    float th_sum = 0.f; unsigned th_cnt = 0u;
    #pragma unroll
    for (int mt = 2; mt < 4; ++mt) {
        #pragma unroll
        for (int half = 0; half < 2; ++half) {
            int b = (mt - 2) * 16 + half * 8 + g;
            float nth = g_nth[b];
            #pragma unroll
            for (int nt = 0; nt < 2; ++nt) {
                int c0 = colbase + nt * 8;
                float s0 = acc[mt][nt][half * 2];
                float s1 = acc[mt][nt][half * 2 + 1];
                if (c0 < Csz && nth < s0 && s0 < 0.9999f)     { th_sum += log1pf(expf(s0)); th_cnt++; }
                if (c0 + 1 < Csz && nth < s1 && s1 < 0.9999f) { th_sum += log1pf(expf(s1)); th_cnt++; }
            }
        }
    }
    #pragma unroll
    for (int o = 16; o; o >>= 1) {
        th_sum += __shfl_xor_sync(0xffffffffu, th_sum, o);
        th_cnt += __shfl_xor_sync(0xffffffffu, th_cnt, o);
    }
    if ((tid & 31) == 0 && th_cnt) { atomicAdd(&g_th_sum, th_sum); atomicAdd(&g_th_cnt, th_cnt); }

    __syncthreads();
    if (tid < 32) {
        g_pmax[tid * NBP + bx] = decf(s_max[tid]);
        g_psum[tid * NBP + bx] = s_sum[tid];
    }
}

// ---------------- final: partial-LSE reduce + h_loss + assemble ----------------
__global__ void final_kernel(const int* __restrict__ targets, float* loss_out) {
    __shared__ float s_bu[32];
    int tid = threadIdx.x, w = tid >> 5, lane = tid & 31;

    {   // warp w reduces row w's 313 partials
        float M = -3.0e38f;
        for (int p = lane; p < NBLK; p += 32) M = fmaxf(M, g_pmax[w * NBP + p]);
        #pragma unroll
        for (int o = 16; o; o >>= 1) M = fmaxf(M, __shfl_xor_sync(0xffffffffu, M, o));
        float S = 0.f;
        for (int p = lane; p < NBLK; p += 32)
            S += expf(g_pmax[w * NBP + p] - M) * g_psum[w * NBP + p];
        #pragma unroll
        for (int o = 16; o; o >>= 1) S += __shfl_xor_sync(0xffffffffu, S, o);
        if (lane == 0) s_bu[w] = M + logf(S) - g_tgt[w];
    }
    __syncthreads();

    if (w == 0) {
        int i = lane;
        int tg = targets[i];
        float bu_i = s_bu[i];
        float mn = 2.f, mx = -2.f;
        for (int j = 0; j < 32; j++) {
            int tgj = __shfl_sync(0xffffffffu, tg, j);
            float s = g_sims[i * 32 + j];
            if (tg == tgj && j != i) { mn = fminf(mn, s); mx = fmaxf(mx, s); }
        }
        float nthr = mn - 0.3f, pthr = mx - 0.2f;
        float ps = 0.f, ns = 0.f, pc = 0.f, nc = 0.f;
        for (int j = 0; j < 32; j++) {
            int tgj = __shfl_sync(0xffffffffu, tg, j);
            float s = g_sims[i * 32 + j];
            bool same = (tg == tgj);
            if (same && j != i && s < pthr) { ps += log1pf(expf(-s)); pc += 1.f; }
            if (!same && s > nthr)          { ns += log1pf(expf(s));  nc += 1.f; }
        }
        #pragma unroll
        for (int o = 16; o; o >>= 1) {
            bu_i += __shfl_xor_sync(0xffffffffu, bu_i, o);
            ps += __shfl_xor_sync(0xffffffffu, ps, o);
            ns += __shfl_xor_sync(0xffffffffu, ns, o);
            pc += __shfl_xor_sync(0xffffffffu, pc, o);
            nc += __shfl_xor_sync(0xffffffffu, nc, o);
        }
        if (i == 0) {
            float h  = (pc > 0.f ? ps / pc : 0.f) + (nc > 0.f ? ns / nc : 0.f);
            float th = (g_active && g_th_cnt > 0u) ? g_th_sum / (float)g_th_cnt : 0.f;
            float loss = bu_i * (1.f / 32.f) + h + 3.f * th;
            if (loss_out) loss_out[0] = loss;
        }
    }
}

// ---------------- launch ----------------
extern "C" void kernel_launch(void* const* d_in, const int* in_sizes, int n_in,
                              void* d_out, int out_size) {
    const float* inputs  = (const float*)d_in[0];
    const float* V       = (const float*)d_in[1];
    const int*   targets = (const int*)d_in[2];
    float* out = (float*)d_out;

    const int BC = Bsz * Csz;
    int write_out = (out_size >= BC) ? 1 : 0;
    int off = write_out ? (out_size - BC) : 0;
    float* outp = write_out ? (out + off) : nullptr;
    float* loss_out = (off >= 1 || out_size < BC) ? out : nullptr;

    prep_kernel<<<32, 256>>>(inputs, V, targets);
    fused_gemm<<<NBLK + 32, 256>>>(V, targets, outp, write_out);
    final_kernel<<<1, 1024>>>(targets, loss_out);
}

// round 9
// speedup vs baseline: 4.7234x; 1.0002x over previous
#include <cuda_runtime.h>
#include <math.h>
#include <stdint.h>

#define Bsz  32
#define Csz  40000
#define Dsz  2048
#define BN   160
#define NBLK 250              // 250*160 = 40000 exactly
#define NBP  256
#define BK   32
#define NTIL 64               // 2048/32
#define NS   3

// dynamic smem (bytes)
#define VSTB  23040           // 160 rows * 36 floats * 4
#define ASTB  8192            // 2048 floats
#define OFF_A    (NS * VSTB)              // 69120
#define OFF_CTRL (OFF_A + NS * ASTB)      // 93696
#define OFF_MAX  (OFF_CTRL)               // 32 u32
#define OFF_SUM  (OFF_CTRL + 128)         // 32 f32
#define OFF_TG   (OFF_CTRL + 256)         // 32 i32
#define OFF_RS   (OFF_CTRL + 384)         // 160 f32
#define SMEM_TOT (OFF_CTRL + 384 + 640)   // 94720

// ---------------- device scratch ----------------
__device__ float    g_Ap[64 * Dsz];    // permuted RN-tf32 A (rows 0-31 inputs, 32-63 V[targets])
__device__ float    g_ni[Bsz * Dsz];
__device__ float    g_nth[Bsz];
__device__ float    g_sims[Bsz * Bsz];
__device__ float    g_pmax[Bsz * NBP];
__device__ float    g_psum[Bsz * NBP];
__device__ float    g_tgt[Bsz];
__device__ float    g_th_sum;
__device__ unsigned g_th_cnt;
__device__ int      g_active;

__device__ __forceinline__ unsigned encf(float f) {
    unsigned b = __float_as_uint(f);
    return (b & 0x80000000u) ? ~b : (b | 0x80000000u);
}
__device__ __forceinline__ float decf(unsigned u) {
    return (u & 0x80000000u) ? __uint_as_float(u ^ 0x80000000u)
                             : __uint_as_float(~u);
}
__device__ __forceinline__ float to_tf32(float x) {
    unsigned r; asm("cvt.rna.tf32.f32 %0, %1;" : "=r"(r) : "f"(x));
    return __uint_as_float(r);
}
__device__ __forceinline__ unsigned to_tf32_b(float x) {
    unsigned r; asm("cvt.rna.tf32.f32 %0, %1;" : "=r"(r) : "f"(x));
    return r;
}
__device__ __forceinline__ void mma_tf32(float* c, const unsigned* a,
                                         unsigned b0, unsigned b1) {
    asm volatile(
        "mma.sync.aligned.m16n8k8.row.col.f32.tf32.tf32.f32 "
        "{%0,%1,%2,%3}, {%4,%5,%6,%7}, {%8,%9}, {%0,%1,%2,%3};"
        : "+f"(c[0]), "+f"(c[1]), "+f"(c[2]), "+f"(c[3])
        : "r"(a[0]), "r"(a[1]), "r"(a[2]), "r"(a[3]), "r"(b0), "r"(b1));
}

// permuted A index: [tile][c][mt][lane][frag]
__device__ __forceinline__ int apos(int row, int k) {
    int t = k >> 5, c = (k >> 3) & 3, hh = (k >> 2) & 1, t4 = k & 3;
    int mt = row >> 4, g = row & 7, rr = (row >> 3) & 1;
    return ((t * 4 + c) * 4 + mt) * 128 + (g * 4 + t4) * 4 + (hh * 2 + rr);
}

#define CP16(d, s)  asm volatile("cp.async.cg.shared.global [%0],[%1],16;" :: "r"(d), "l"(s))
#define CPCOMMIT()  asm volatile("cp.async.commit_group;")
#define CPWAIT2()   asm volatile("cp.async.wait_group 2;")

// ---------------- prep ----------------
__global__ void prep_kernel(const float* __restrict__ inputs,
                            const float* __restrict__ V,
                            const int* __restrict__ targets) {
    __shared__ float sh[8];
    __shared__ float s_norm;
    int b = blockIdx.x, tid = threadIdx.x;
    const float* x = inputs + b * Dsz;

    float ss = 0.f;
    for (int k = tid; k < Dsz; k += 256) {
        float v = x[k];
        g_Ap[apos(b, k)] = to_tf32(v);
        ss += v * v;
    }
    #pragma unroll
    for (int o = 16; o; o >>= 1) ss += __shfl_xor_sync(0xffffffffu, ss, o);
    if ((tid & 31) == 0) sh[tid >> 5] = ss;
    __syncthreads();
    if (tid == 0) {
        float t = 0.f;
        for (int i = 0; i < 8; i++) t += sh[i];
        s_norm = sqrtf(t);
    }
    __syncthreads();
    float inv = 1.f / s_norm;

    int tb = targets[b];
    const float* vt = V + (size_t)tb * Dsz;
    float dot = 0.f;
    for (int k = tid; k < Dsz; k += 256) {
        float nv = x[k] * inv;
        g_ni[b * Dsz + k] = nv;
        float w = vt[k];
        g_Ap[apos(32 + b, k)] = to_tf32(w);
        dot += nv * w;
    }
    #pragma unroll
    for (int o = 16; o; o >>= 1) dot += __shfl_xor_sync(0xffffffffu, dot, o);
    __syncthreads();
    if ((tid & 31) == 0) sh[tid >> 5] = dot;
    __syncthreads();
    if (tid == 0) {
        float t = 0.f;
        for (int i = 0; i < 8; i++) t += sh[i];
        g_nth[b] = t - 0.3f;
        if (b == 0) { g_th_sum = 0.f; g_th_cnt = 0u; g_active = 1; }
    }
}

// ---------------- fused GEMM + softmax partials + th-loss (+sims) ----------------
__global__ void __launch_bounds__(256, 2)
fused_gemm(const float* __restrict__ V, const int* __restrict__ targets,
           float* __restrict__ outp, int write_out) {
    extern __shared__ __align__(16) char smem[];
    int bx = blockIdx.x;
    int tid = threadIdx.x;

    if (bx >= NBLK) {
        // ---- batch sims in gemm tail shadow ----
        int i = bx - NBLK;
        int w = tid >> 5, lane = tid & 31;
        const float4* a = (const float4*)(g_ni + (size_t)i * Dsz);
        for (int j = w; j < 32; j += 8) {
            const float4* c = (const float4*)(g_ni + (size_t)j * Dsz);
            float d = 0.f;
            for (int k = lane; k < Dsz / 4; k += 32) {
                float4 x = a[k], y = c[k];
                d += x.x * y.x + x.y * y.y + x.z * y.z + x.w * y.w;
            }
            #pragma unroll
            for (int o = 16; o; o >>= 1) d += __shfl_xor_sync(0xffffffffu, d, o);
            if (lane == 0) g_sims[i * 32 + j] = d;
        }
        return;
    }

    float* smf = (float*)smem;
    uint32_t sb = (uint32_t)__cvta_generic_to_shared(smem);
    int lane = tid & 31, w = tid >> 5;
    int wm = w >> 2, wn = w & 3;
    int g = lane >> 2, t4 = lane & 3;
    int j0 = bx * BN;

    unsigned* s_max = (unsigned*)(smem + OFF_MAX);
    float*    s_sum = (float*)(smem + OFF_SUM);
    int*      s_tg  = (int*)(smem + OFF_TG);
    float*    s_rs  = (float*)(smem + OFF_RS);

    if (tid < 32) { s_max[tid] = encf(-3.0e38f); s_sum[tid] = 0.f; s_tg[tid] = targets[tid]; }
    for (int i = tid; i < BN; i += 256) s_rs[i] = 0.f;

    // V loader: 5 chunks of 16B per thread; chunk id = tid*5+i -> (row, part)
    int vrow[5], vpart[5];
    const float* vsrc[5];
    unsigned vdst[5];
    #pragma unroll
    for (int i = 0; i < 5; i++) {
        int id = tid * 5 + i;
        vrow[i] = id >> 3; vpart[i] = id & 7;
        vsrc[i] = V + (size_t)(j0 + vrow[i]) * Dsz + vpart[i] * 4;
        vdst[i] = sb + vrow[i] * 144 + vpart[i] * 16;
    }
    // A loader: 2 chunks of 16B per thread
    const float* asrc = g_Ap + tid * 8;
    unsigned adst = sb + OFF_A + tid * 32;

    float acc[2][5][4];
    #pragma unroll
    for (int i = 0; i < 2; i++)
        #pragma unroll
        for (int j = 0; j < 5; j++)
            #pragma unroll
            for (int k = 0; k < 4; k++) acc[i][j][k] = 0.f;
    float racc[5];
    #pragma unroll
    for (int i = 0; i < 5; i++) racc[i] = 0.f;

    // prologue: stages 0..2
    #pragma unroll
    for (int t = 0; t < NS; ++t) {
        #pragma unroll
        for (int i = 0; i < 5; i++) CP16(vdst[i] + t * VSTB, vsrc[i] + t * BK);
        CP16(adst + t * ASTB, asrc + (size_t)t * 2048);
        CP16(adst + t * ASTB + 16, asrc + (size_t)t * 2048 + 4);
        CPCOMMIT();
    }

    for (int t = 0; t < NTIL; ++t) {
        CPWAIT2();
        __syncthreads();
        int s = t % NS;
        const float* Vst = smf + s * (VSTB / 4);
        const float* Ast = smf + (OFF_A / 4) + s * 2048;

        #pragma unroll
        for (int c = 0; c < 4; ++c) {
            unsigned af[2][4];
            #pragma unroll
            for (int mt = 0; mt < 2; ++mt) {
                int MT = wm * 2 + mt;
                float4 fa = *(const float4*)(Ast + (c * 4 + MT) * 128 + lane * 4);
                af[mt][0] = __float_as_uint(fa.x); af[mt][1] = __float_as_uint(fa.y);
                af[mt][2] = __float_as_uint(fa.z); af[mt][3] = __float_as_uint(fa.w);
            }
            #pragma unroll
            for (int nt = 0; nt < 5; ++nt) {
                int vr = wn * 40 + nt * 8 + g;
                float b0f = Vst[vr * 36 + c * 8 + t4];
                float b1f = Vst[vr * 36 + c * 8 + 4 + t4];
                unsigned b0 = to_tf32_b(b0f), b1 = to_tf32_b(b1f);
                mma_tf32(acc[0][nt], af[0], b0, b1);
                mma_tf32(acc[1][nt], af[1], b0, b1);
            }
        }
        // row-sum partials ('active' check) from own chunks
        #pragma unroll
        for (int i = 0; i < 5; i++) {
            float4 q = *(const float4*)(smf + s * (VSTB / 4) + vrow[i] * 36 + vpart[i] * 4);
            racc[i] += q.x + q.y + q.z + q.w;
        }
        __syncthreads();
        int tn = t + NS;
        if (tn < NTIL) {
            int s2 = s;
            #pragma unroll
            for (int i = 0; i < 5; i++) CP16(vdst[i] + s2 * VSTB, vsrc[i] + tn * BK);
            CP16(adst + s2 * ASTB, asrc + (size_t)tn * 2048);
            CP16(adst + s2 * ASTB + 16, asrc + (size_t)tn * 2048 + 4);
        }
        CPCOMMIT();
    }

    // finalize row sums -> active check
    #pragma unroll
    for (int i = 0; i < 5; i++) atomicAdd(&s_rs[vrow[i]], racc[i]);

    // phase 1: block row maxima (wm0 warps own logit rows 0-31)
    if (wm == 0) {
        #pragma unroll
        for (int mt = 0; mt < 2; ++mt) {
            #pragma unroll
            for (int half = 0; half < 2; ++half) {
                int row = mt * 16 + half * 8 + g;
                float rmax = -3.0e38f;
                #pragma unroll
                for (int nt = 0; nt < 5; ++nt) {
                    rmax = fmaxf(rmax, acc[mt][nt][half * 2]);
                    rmax = fmaxf(rmax, acc[mt][nt][half * 2 + 1]);
                }
                rmax *= 10.f;
                rmax = fmaxf(rmax, __shfl_xor_sync(0xffffffffu, rmax, 1));
                rmax = fmaxf(rmax, __shfl_xor_sync(0xffffffffu, rmax, 2));
                if (t4 == 0) atomicMax(&s_max[row], encf(rmax));
            }
        }
    }
    __syncthreads();

    if (tid < BN && s_rs[tid] == 0.f) g_active = 0;

    if (wm == 0) {
        // phase 2: expsum + store (scalar f32 — outp may be 4B-aligned only) + target capture
        #pragma unroll
        for (int mt = 0; mt < 2; ++mt) {
            #pragma unroll
            for (int half = 0; half < 2; ++half) {
                int row = mt * 16 + half * 8 + g;
                float m = decf(s_max[row]);
                int tg = s_tg[row];
                float es = 0.f;
                #pragma unroll
                for (int nt = 0; nt < 5; ++nt) {
                    int c0 = j0 + wn * 40 + nt * 8 + 2 * t4;
                    float o0 = acc[mt][nt][half * 2] * 10.f;
                    float o1 = acc[mt][nt][half * 2 + 1] * 10.f;
                    if (write_out) {
                        outp[(size_t)row * Csz + c0]     = o0;
                        outp[(size_t)row * Csz + c0 + 1] = o1;
                    }
                    if (c0 == tg)     g_tgt[row] = o0;
                    if (c0 + 1 == tg) g_tgt[row] = o1;
                    es += expf(o0 - m) + expf(o1 - m);
                }
                es += __shfl_xor_sync(0xffffffffu, es, 1);
                es += __shfl_xor_sync(0xffffffffu, es, 2);
                if (t4 == 0) atomicAdd(&s_sum[row], es);
            }
        }
    } else {
        // th-loss (m rows 32-63 = nsims rows 0-31)
        float ths = 0.f; unsigned thc = 0u;
        #pragma unroll
        for (int mt = 0; mt < 2; ++mt) {
            #pragma unroll
            for (int half = 0; half < 2; ++half) {
                int b = mt * 16 + half * 8 + g;
                float nth = g_nth[b];
                #pragma unroll
                for (int nt = 0; nt < 5; ++nt) {
                    float s0 = acc[mt][nt][half * 2];
                    float s1 = acc[mt][nt][half * 2 + 1];
                    if (nth < s0 && s0 < 0.9999f) { ths += log1pf(expf(s0)); thc++; }
                    if (nth < s1 && s1 < 0.9999f) { ths += log1pf(expf(s1)); thc++; }
                }
            }
        }
        #pragma unroll
        for (int o = 16; o; o >>= 1) {
            ths += __shfl_xor_sync(0xffffffffu, ths, o);
            thc += __shfl_xor_sync(0xffffffffu, thc, o);
        }
        if (lane == 0 && thc) { atomicAdd(&g_th_sum, ths); atomicAdd(&g_th_cnt, thc); }
    }
    __syncthreads();
    if (tid < 32) {
        g_pmax[tid * NBP + bx] = decf(s_max[tid]);
        g_psum[tid * NBP + bx] = s_sum[tid];
    }
}

// ---------------- final: partial-LSE reduce + h_loss + assemble ----------------
__global__ void final_kernel(const int* __restrict__ targets, float* loss_out) {
    __shared__ float s_bu[32];
    int tid = threadIdx.x, w = tid >> 5, lane = tid & 31;

    {
        float M = -3.0e38f;
        for (int p = lane; p < NBLK; p += 32) M = fmaxf(M, g_pmax[w * NBP + p]);
        #pragma unroll
        for (int o = 16; o; o >>= 1) M = fmaxf(M, __shfl_xor_sync(0xffffffffu, M, o));
        float S = 0.f;
        for (int p = lane; p < NBLK; p += 32)
            S += expf(g_pmax[w * NBP + p] - M) * g_psum[w * NBP + p];
        #pragma unroll
        for (int o = 16; o; o >>= 1) S += __shfl_xor_sync(0xffffffffu, S, o);
        if (lane == 0) s_bu[w] = M + logf(S) - g_tgt[w];
    }
    __syncthreads();

    if (w == 0) {
        int i = lane;
        int tg = targets[i];
        float bu_i = s_bu[i];
        float mn = 2.f, mx = -2.f;
        for (int j = 0; j < 32; j++) {
            int tgj = __shfl_sync(0xffffffffu, tg, j);
            float s = g_sims[i * 32 + j];
            if (tg == tgj && j != i) { mn = fminf(mn, s); mx = fmaxf(mx, s); }
        }
        float nthr = mn - 0.3f, pthr = mx - 0.2f;
        float ps = 0.f, ns = 0.f, pc = 0.f, nc = 0.f;
        for (int j = 0; j < 32; j++) {
            int tgj = __shfl_sync(0xffffffffu, tg, j);
            float s = g_sims[i * 32 + j];
            bool same = (tg == tgj);
            if (same && j != i && s < pthr) { ps += log1pf(expf(-s)); pc += 1.f; }
            if (!same && s > nthr)          { ns += log1pf(expf(s));  nc += 1.f; }
        }
        #pragma unroll
        for (int o = 16; o; o >>= 1) {
            bu_i += __shfl_xor_sync(0xffffffffu, bu_i, o);
            ps += __shfl_xor_sync(0xffffffffu, ps, o);
            ns += __shfl_xor_sync(0xffffffffu, ns, o);
            pc += __shfl_xor_sync(0xffffffffu, pc, o);
            nc += __shfl_xor_sync(0xffffffffu, nc, o);
        }
        if (i == 0) {
            float h  = (pc > 0.f ? ps / pc : 0.f) + (nc > 0.f ? ns / nc : 0.f);
            float th = (g_active && g_th_cnt > 0u) ? g_th_sum / (float)g_th_cnt : 0.f;
            float loss = bu_i * (1.f / 32.f) + h + 3.f * th;
            if (loss_out) loss_out[0] = loss;
        }
    }
}

// ---------------- launch ----------------
extern "C" void kernel_launch(void* const* d_in, const int* in_sizes, int n_in,
                              void* d_out, int out_size) {
    const float* inputs  = (const float*)d_in[0];
    const float* V       = (const float*)d_in[1];
    const int*   targets = (const int*)d_in[2];
    float* out = (float*)d_out;

    const int BC = Bsz * Csz;
    int write_out = (out_size >= BC) ? 1 : 0;
    int off = write_out ? (out_size - BC) : 0;
    float* outp = write_out ? (out + off) : nullptr;
    float* loss_out = (off >= 1 || out_size < BC) ? out : nullptr;

    cudaFuncSetAttribute(fused_gemm, cudaFuncAttributeMaxDynamicSharedMemorySize, SMEM_TOT);

    prep_kernel<<<32, 256>>>(inputs, V, targets);
    fused_gemm<<<NBLK + 32, 256, SMEM_TOT>>>(V, targets, outp, write_out);
    final_kernel<<<1, 1024>>>(targets, loss_out);
}

// round 10
// speedup vs baseline: 4.7564x; 1.0070x over previous
#include <cuda_runtime.h>
#include <math.h>
#include <stdint.h>

#define Bsz  32
#define Csz  40000
#define Dsz  2048
#define BN   160
#define NBLK 250              // 250*160 = 40000 exactly
#define NBP  256
#define BK   32
#define NTIL 64               // 2048/32
#define NS   3
#define NU   16               // max unique targets (reference: randint(0,16))

// dynamic smem (bytes)
#define VSTB  23040           // 160 rows * 36 floats * 4
#define ASTB  6144            // 48 rows * 32 floats * 4 per k-tile
#define OFF_A    (NS * VSTB)              // 69120
#define OFF_CTRL (OFF_A + NS * ASTB)      // 87552
#define OFF_MAX  (OFF_CTRL)               // 32 u32
#define OFF_SUM  (OFF_CTRL + 128)         // 32 f32
#define OFF_TG   (OFF_CTRL + 256)         // 32 i32
#define OFF_RS   (OFF_CTRL + 384)         // 160 f32
#define OFF_NTH  (OFF_CTRL + 1024)        // 32 f32
#define SMEM_TOT (OFF_CTRL + 1024 + 128)  // 88704

// ---------------- device scratch ----------------
__device__ float    g_Ap[48 * Dsz];    // permuted RN-tf32: rows 0-31 inputs, 32-47 unique V[targets]
__device__ float    g_ni[Bsz * Dsz];
__device__ float    g_nth[Bsz];
__device__ int      g_uval[NU];        // unique target values
__device__ unsigned g_umask[NU];       // bitmask of b's per unique slot
__device__ float    g_sims[Bsz * Bsz];
__device__ float    g_pmax[Bsz * NBP];
__device__ float    g_psum[Bsz * NBP];
__device__ float    g_tgt[Bsz];
__device__ float    g_th_sum;
__device__ unsigned g_th_cnt;
__device__ int      g_active;

__device__ __forceinline__ unsigned encf(float f) {
    unsigned b = __float_as_uint(f);
    return (b & 0x80000000u) ? ~b : (b | 0x80000000u);
}
__device__ __forceinline__ float decf(unsigned u) {
    return (u & 0x80000000u) ? __uint_as_float(u ^ 0x80000000u)
                             : __uint_as_float(~u);
}
__device__ __forceinline__ float to_tf32(float x) {
    unsigned r; asm("cvt.rna.tf32.f32 %0, %1;" : "=r"(r) : "f"(x));
    return __uint_as_float(r);
}
__device__ __forceinline__ unsigned to_tf32_b(float x) {
    unsigned r; asm("cvt.rna.tf32.f32 %0, %1;" : "=r"(r) : "f"(x));
    return r;
}
__device__ __forceinline__ void mma_tf32(float* c, const unsigned* a,
                                         unsigned b0, unsigned b1) {
    asm volatile(
        "mma.sync.aligned.m16n8k8.row.col.f32.tf32.tf32.f32 "
        "{%0,%1,%2,%3}, {%4,%5,%6,%7}, {%8,%9}, {%0,%1,%2,%3};"
        : "+f"(c[0]), "+f"(c[1]), "+f"(c[2]), "+f"(c[3])
        : "r"(a[0]), "r"(a[1]), "r"(a[2]), "r"(a[3]), "r"(b0), "r"(b1));
}

// permuted A index: [tile][c][mt:3][lane][frag], rows 0-47
__device__ __forceinline__ int apos(int row, int k) {
    int t = k >> 5, c = (k >> 3) & 3, hh = (k >> 2) & 1, t4 = k & 3;
    int mt = row >> 4, g = row & 7, rr = (row >> 3) & 1;
    return ((t * 4 + c) * 3 + mt) * 128 + (g * 4 + t4) * 4 + (hh * 2 + rr);
}

#define CP16(d, s)  asm volatile("cp.async.cg.shared.global [%0],[%1],16;" :: "r"(d), "l"(s))
#define CPCOMMIT()  asm volatile("cp.async.commit_group;")
#define CPWAIT2()   asm volatile("cp.async.wait_group 2;")

// ---------------- dedup: unique targets + per-slot b-bitmask ----------------
__global__ void dedup_kernel(const int* __restrict__ targets) {
    if (threadIdx.x == 0) {
        int uval[NU]; unsigned um[NU]; int nu = 0;
        int t0 = targets[0];
        for (int b = 0; b < Bsz; b++) {
            int t = targets[b]; int f = -1;
            for (int u = 0; u < nu; u++) if (uval[u] == t) { f = u; break; }
            if (f < 0) { f = nu; uval[nu] = t; um[nu] = 0u; nu++; }
            um[f] |= 1u << b;
        }
        for (int u = 0; u < NU; u++) {
            g_uval[u]  = (u < nu) ? uval[u] : t0;
            g_umask[u] = (u < nu) ? um[u] : 0u;
        }
        g_th_sum = 0.f; g_th_cnt = 0u; g_active = 1;
    }
}

// ---------------- prep: blocks 0-31 input rows, 32-47 unique V rows ----------------
__global__ void prep_kernel(const float* __restrict__ inputs,
                            const float* __restrict__ V,
                            const int* __restrict__ targets) {
    __shared__ float sh[8];
    __shared__ float s_norm;
    int b = blockIdx.x, tid = threadIdx.x;

    if (b >= 32) {
        int u = b - 32;
        const float* vr = V + (size_t)g_uval[u] * Dsz;
        for (int k = tid; k < Dsz; k += 256)
            g_Ap[apos(32 + u, k)] = to_tf32(vr[k]);
        return;
    }

    const float* x = inputs + b * Dsz;
    float ss = 0.f;
    for (int k = tid; k < Dsz; k += 256) {
        float v = x[k];
        g_Ap[apos(b, k)] = to_tf32(v);
        ss += v * v;
    }
    #pragma unroll
    for (int o = 16; o; o >>= 1) ss += __shfl_xor_sync(0xffffffffu, ss, o);
    if ((tid & 31) == 0) sh[tid >> 5] = ss;
    __syncthreads();
    if (tid == 0) {
        float t = 0.f;
        for (int i = 0; i < 8; i++) t += sh[i];
        s_norm = sqrtf(t);
    }
    __syncthreads();
    float inv = 1.f / s_norm;

    int tb = targets[b];
    const float* vt = V + (size_t)tb * Dsz;
    float dot = 0.f;
    for (int k = tid; k < Dsz; k += 256) {
        float nv = x[k] * inv;
        g_ni[b * Dsz + k] = nv;
        dot += nv * vt[k];
    }
    #pragma unroll
    for (int o = 16; o; o >>= 1) dot += __shfl_xor_sync(0xffffffffu, dot, o);
    __syncthreads();
    if ((tid & 31) == 0) sh[tid >> 5] = dot;
    __syncthreads();
    if (tid == 0) {
        float t = 0.f;
        for (int i = 0; i < 8; i++) t += sh[i];
        g_nth[b] = t - 0.3f;
    }
}

// ---------------- fused GEMM (M=48) + softmax partials + th-loss (+sims) ----------
__global__ void __launch_bounds__(256, 2)
fused_gemm(const float* __restrict__ V, const int* __restrict__ targets,
           float* __restrict__ outp, int write_out) {
    extern __shared__ __align__(16) char smem[];
    int bx = blockIdx.x;
    int tid = threadIdx.x;

    if (bx >= NBLK) {
        // ---- batch sims in gemm tail shadow ----
        int i = bx - NBLK;
        int w = tid >> 5, lane = tid & 31;
        const float4* a = (const float4*)(g_ni + (size_t)i * Dsz);
        for (int j = w; j < 32; j += 8) {
            const float4* c = (const float4*)(g_ni + (size_t)j * Dsz);
            float d = 0.f;
            for (int k = lane; k < Dsz / 4; k += 32) {
                float4 x = a[k], y = c[k];
                d += x.x * y.x + x.y * y.y + x.z * y.z + x.w * y.w;
            }
            #pragma unroll
            for (int o = 16; o; o >>= 1) d += __shfl_xor_sync(0xffffffffu, d, o);
            if (lane == 0) g_sims[i * 32 + j] = d;
        }
        return;
    }

    float* smf = (float*)smem;
    uint32_t sb = (uint32_t)__cvta_generic_to_shared(smem);
    int lane = tid & 31, w = tid >> 5;
    int wm = w >> 2, wn = w & 3;
    int g = lane >> 2, t4 = lane & 3;
    int j0 = bx * BN;

    unsigned* s_max = (unsigned*)(smem + OFF_MAX);
    float*    s_sum = (float*)(smem + OFF_SUM);
    int*      s_tg  = (int*)(smem + OFF_TG);
    float*    s_rs  = (float*)(smem + OFF_RS);
    float*    s_nth = (float*)(smem + OFF_NTH);

    if (tid < 32) {
        s_max[tid] = encf(-3.0e38f); s_sum[tid] = 0.f;
        s_tg[tid] = targets[tid]; s_nth[tid] = g_nth[tid];
    }
    for (int i = tid; i < BN; i += 256) s_rs[i] = 0.f;

    // V loader: 5 chunks of 16B per thread
    int vrow[5], vpart[5];
    const float* vsrc[5];
    unsigned vdst[5];
    #pragma unroll
    for (int i = 0; i < 5; i++) {
        int id = tid * 5 + i;
        vrow[i] = id >> 3; vpart[i] = id & 7;
        vsrc[i] = V + (size_t)(j0 + vrow[i]) * Dsz + vpart[i] * 4;
        vdst[i] = sb + vrow[i] * 144 + vpart[i] * 16;
    }
    // A loader: 384 chunks of 16B per stage (1536 floats); thread t: chunk t (+ chunk 256+t for t<128)
    unsigned adst0 = sb + OFF_A + tid * 16;
    unsigned adst1 = sb + OFF_A + (256 + tid) * 16;

    float acc[2][5][4];
    #pragma unroll
    for (int i = 0; i < 2; i++)
        #pragma unroll
        for (int j = 0; j < 5; j++)
            #pragma unroll
            for (int k = 0; k < 4; k++) acc[i][j][k] = 0.f;
    float racc[5];
    #pragma unroll
    for (int i = 0; i < 5; i++) racc[i] = 0.f;

    // prologue
    #pragma unroll
    for (int t = 0; t < NS; ++t) {
        #pragma unroll
        for (int i = 0; i < 5; i++) CP16(vdst[i] + t * VSTB, vsrc[i] + t * BK);
        CP16(adst0 + t * ASTB, g_Ap + t * 1536 + tid * 4);
        if (tid < 128) CP16(adst1 + t * ASTB, g_Ap + t * 1536 + (256 + tid) * 4);
        CPCOMMIT();
    }

    for (int t = 0; t < NTIL; ++t) {
        CPWAIT2();
        __syncthreads();
        int s = t % NS;
        const float* Vst = smf + s * (VSTB / 4);
        const float* Ast = smf + (OFF_A / 4) + s * 1536;

        if (wm == 0) {
            #pragma unroll
            for (int c = 0; c < 4; ++c) {
                unsigned af[2][4];
                #pragma unroll
                for (int mt = 0; mt < 2; ++mt) {
                    float4 fa = *(const float4*)(Ast + (c * 3 + mt) * 128 + lane * 4);
                    af[mt][0] = __float_as_uint(fa.x); af[mt][1] = __float_as_uint(fa.y);
                    af[mt][2] = __float_as_uint(fa.z); af[mt][3] = __float_as_uint(fa.w);
                }
                #pragma unroll
                for (int nt = 0; nt < 5; ++nt) {
                    int vr = wn * 40 + nt * 8 + g;
                    unsigned b0 = to_tf32_b(Vst[vr * 36 + c * 8 + t4]);
                    unsigned b1 = to_tf32_b(Vst[vr * 36 + c * 8 + 4 + t4]);
                    mma_tf32(acc[0][nt], af[0], b0, b1);
                    mma_tf32(acc[1][nt], af[1], b0, b1);
                }
            }
        } else {
            #pragma unroll
            for (int c = 0; c < 4; ++c) {
                unsigned af[4];
                float4 fa = *(const float4*)(Ast + (c * 3 + 2) * 128 + lane * 4);
                af[0] = __float_as_uint(fa.x); af[1] = __float_as_uint(fa.y);
                af[2] = __float_as_uint(fa.z); af[3] = __float_as_uint(fa.w);
                #pragma unroll
                for (int nt = 0; nt < 5; ++nt) {
                    int vr = wn * 40 + nt * 8 + g;
                    unsigned b0 = to_tf32_b(Vst[vr * 36 + c * 8 + t4]);
                    unsigned b1 = to_tf32_b(Vst[vr * 36 + c * 8 + 4 + t4]);
                    mma_tf32(acc[0][nt], af, b0, b1);
                }
            }
        }
        // row-sum partials ('active' check)
        #pragma unroll
        for (int i = 0; i < 5; i++) {
            float4 q = *(const float4*)(smf + s * (VSTB / 4) + vrow[i] * 36 + vpart[i] * 4);
            racc[i] += q.x + q.y + q.z + q.w;
        }
        __syncthreads();
        int tn = t + NS;
        if (tn < NTIL) {
            #pragma unroll
            for (int i = 0; i < 5; i++) CP16(vdst[i] + s * VSTB, vsrc[i] + tn * BK);
            CP16(adst0 + s * ASTB, g_Ap + tn * 1536 + tid * 4);
            if (tid < 128) CP16(adst1 + s * ASTB, g_Ap + tn * 1536 + (256 + tid) * 4);
        }
        CPCOMMIT();
    }

    #pragma unroll
    for (int i = 0; i < 5; i++) atomicAdd(&s_rs[vrow[i]], racc[i]);

    // phase 1: block row maxima (wm0 warps own logit rows 0-31)
    if (wm == 0) {
        #pragma unroll
        for (int mt = 0; mt < 2; ++mt) {
            #pragma unroll
            for (int half = 0; half < 2; ++half) {
                int row = mt * 16 + half * 8 + g;
                float rmax = -3.0e38f;
                #pragma unroll
                for (int nt = 0; nt < 5; ++nt) {
                    rmax = fmaxf(rmax, acc[mt][nt][half * 2]);
                    rmax = fmaxf(rmax, acc[mt][nt][half * 2 + 1]);
                }
                rmax *= 10.f;
                rmax = fmaxf(rmax, __shfl_xor_sync(0xffffffffu, rmax, 1));
                rmax = fmaxf(rmax, __shfl_xor_sync(0xffffffffu, rmax, 2));
                if (t4 == 0) atomicMax(&s_max[row], encf(rmax));
            }
        }
    }
    __syncthreads();

    if (tid < BN && s_rs[tid] == 0.f) g_active = 0;

    if (wm == 0) {
        // phase 2: expsum + scalar store + target capture
        #pragma unroll
        for (int mt = 0; mt < 2; ++mt) {
            #pragma unroll
            for (int half = 0; half < 2; ++half) {
                int row = mt * 16 + half * 8 + g;
                float m = decf(s_max[row]);
                int tg = s_tg[row];
                float es = 0.f;
                #pragma unroll
                for (int nt = 0; nt < 5; ++nt) {
                    int c0 = j0 + wn * 40 + nt * 8 + 2 * t4;
                    float o0 = acc[mt][nt][half * 2] * 10.f;
                    float o1 = acc[mt][nt][half * 2 + 1] * 10.f;
                    if (write_out) {
                        outp[(size_t)row * Csz + c0]     = o0;
                        outp[(size_t)row * Csz + c0 + 1] = o1;
                    }
                    if (c0 == tg)     g_tgt[row] = o0;
                    if (c0 + 1 == tg) g_tgt[row] = o1;
                    es += expf(o0 - m) + expf(o1 - m);
                }
                es += __shfl_xor_sync(0xffffffffu, es, 1);
                es += __shfl_xor_sync(0xffffffffu, es, 2);
                if (t4 == 0) atomicAdd(&s_sum[row], es);
            }
        }
    } else {
        // th-loss: unique slot rows; per-slot b-bitmask re-applies per-b thresholds
        unsigned um[2] = { g_umask[g], g_umask[8 + g] };
        float ths = 0.f; unsigned thc = 0u;
        #pragma unroll
        for (int half = 0; half < 2; ++half) {    // half==rr: slot = half*8+g
            unsigned mask = um[half];
            if (!mask) continue;
            #pragma unroll
            for (int nt = 0; nt < 5; ++nt) {
                #pragma unroll
                for (int q = 0; q < 2; ++q) {     // q==hh (column pair)
                    float sval = acc[0][nt][q * 2 + half];
                    if (sval < 0.9999f) {
                        float sp = log1pf(expf(sval));
                        unsigned mm = mask;
                        while (mm) {
                            int b = __ffs(mm) - 1; mm &= mm - 1;
                            if (s_nth[b] < sval) { ths += sp; thc++; }
                        }
                    }
                }
            }
        }
        #pragma unroll
        for (int o = 16; o; o >>= 1) {
            ths += __shfl_xor_sync(0xffffffffu, ths, o);
            thc += __shfl_xor_sync(0xffffffffu, thc, o);
        }
        if (lane == 0 && thc) { atomicAdd(&g_th_sum, ths); atomicAdd(&g_th_cnt, thc); }
    }
    __syncthreads();
    if (tid < 32) {
        g_pmax[tid * NBP + bx] = decf(s_max[tid]);
        g_psum[tid * NBP + bx] = s_sum[tid];
    }
}

// ---------------- final: partial-LSE reduce + h_loss + assemble ----------------
__global__ void final_kernel(const int* __restrict__ targets, float* loss_out) {
    __shared__ float s_bu[32];
    int tid = threadIdx.x, w = tid >> 5, lane = tid & 31;

    {
        float M = -3.0e38f;
        for (int p = lane; p < NBLK; p += 32) M = fmaxf(M, g_pmax[w * NBP + p]);
        #pragma unroll
        for (int o = 16; o; o >>= 1) M = fmaxf(M, __shfl_xor_sync(0xffffffffu, M, o));
        float S = 0.f;
        for (int p = lane; p < NBLK; p += 32)
            S += expf(g_pmax[w * NBP + p] - M) * g_psum[w * NBP + p];
        #pragma unroll
        for (int o = 16; o; o >>= 1) S += __shfl_xor_sync(0xffffffffu, S, o);
        if (lane == 0) s_bu[w] = M + logf(S) - g_tgt[w];
    }
    __syncthreads();

    if (w == 0) {
        int i = lane;
        int tg = targets[i];
        float bu_i = s_bu[i];
        float mn = 2.f, mx = -2.f;
        for (int j = 0; j < 32; j++) {
            int tgj = __shfl_sync(0xffffffffu, tg, j);
            float s = g_sims[i * 32 + j];
            if (tg == tgj && j != i) { mn = fminf(mn, s); mx = fmaxf(mx, s); }
        }
        float nthr = mn - 0.3f, pthr = mx - 0.2f;
        float ps = 0.f, ns = 0.f, pc = 0.f, nc = 0.f;
        for (int j = 0; j < 32; j++) {
            int tgj = __shfl_sync(0xffffffffu, tg, j);
            float s = g_sims[i * 32 + j];
            bool same = (tg == tgj);
            if (same && j != i && s < pthr) { ps += log1pf(expf(-s)); pc += 1.f; }
            if (!same && s > nthr)          { ns += log1pf(expf(s));  nc += 1.f; }
        }
        #pragma unroll
        for (int o = 16; o; o >>= 1) {
            bu_i += __shfl_xor_sync(0xffffffffu, bu_i, o);
            ps += __shfl_xor_sync(0xffffffffu, ps, o);
            ns += __shfl_xor_sync(0xffffffffu, ns, o);
            pc += __shfl_xor_sync(0xffffffffu, pc, o);
            nc += __shfl_xor_sync(0xffffffffu, nc, o);
        }
        if (i == 0) {
            float h  = (pc > 0.f ? ps / pc : 0.f) + (nc > 0.f ? ns / nc : 0.f);
            float th = (g_active && g_th_cnt > 0u) ? g_th_sum / (float)g_th_cnt : 0.f;
            float loss = bu_i * (1.f / 32.f) + h + 3.f * th;
            if (loss_out) loss_out[0] = loss;
        }
    }
}

// ---------------- launch ----------------
extern "C" void kernel_launch(void* const* d_in, const int* in_sizes, int n_in,
                              void* d_out, int out_size) {
    const float* inputs  = (const float*)d_in[0];
    const float* V       = (const float*)d_in[1];
    const int*   targets = (const int*)d_in[2];
    float* out = (float*)d_out;

    const int BC = Bsz * Csz;
    int write_out = (out_size >= BC) ? 1 : 0;
    int off = write_out ? (out_size - BC) : 0;
    float* outp = write_out ? (out + off) : nullptr;
    float* loss_out = (off >= 1 || out_size < BC) ? out : nullptr;

    cudaFuncSetAttribute(fused_gemm, cudaFuncAttributeMaxDynamicSharedMemorySize, SMEM_TOT);

    dedup_kernel<<<1, 32>>>(targets);
    prep_kernel<<<48, 256>>>(inputs, V, targets);
    fused_gemm<<<NBLK + 32, 256, SMEM_TOT>>>(V, targets, outp, write_out);
    final_kernel<<<1, 1024>>>(targets, loss_out);
}